// round 16
// baseline (speedup 1.0000x reference)
#include <cuda_runtime.h>
#include <cuda_bf16.h>
#include <cuda_fp16.h>
#include <cstdint>

#define NB   2
#define SEQ  2048
#define DM   1024
#define NH   16
#define HD   64
#define ROWS (NB*SEQ)          // 4096
// softmax scale 1/sqrt(64) folded into Q projection together with log2(e):
#define QSCALE 0.18033688011112042f   // 0.125 * log2(e)

// ---------------------------------------------------------------------------
// Scratch (allocation-free: __device__ globals)
// ---------------------------------------------------------------------------
#define PROJN ((size_t)NH*NB*SEQ*HD)     // 4M elems
__device__ __align__(256) __half g_qf[PROJN];                       // fp16 Q
__device__ __align__(256) __half g_kf[PROJN];                       // fp16 K
__device__ __align__(256) __half g_vf[PROJN];                       // fp16 V
__device__ __align__(256) __half g_xf[3][(size_t)ROWS*DM];          // fp16 inputs
__device__ __align__(256) __half g_wfh[4][(size_t)DM*DM];           // fp16 W hi
__device__ __align__(256) __half g_wfl[4][(size_t)DM*DM];           // fp16 W lo
__device__ __align__(256) __half g_yf[(size_t)ROWS*DM];             // fp16 Y

// ---------------------------------------------------------------------------
// PTX helpers (baseline sm_80+ features: mma.sync / ldmatrix / cp.async)
// ---------------------------------------------------------------------------
__device__ __forceinline__ uint32_t smem_u32(const void* p) {
    uint32_t a;
    asm("{ .reg .u64 t; cvta.to.shared.u64 t, %1; cvt.u32.u64 %0, t; }"
        : "=r"(a) : "l"(p));
    return a;
}

#define CP_ASYNC16(dst, src) \
    asm volatile("cp.async.cg.shared.global [%0], [%1], 16;" :: "r"(dst), "l"(src))
#define CP_COMMIT() asm volatile("cp.async.commit_group;" ::: "memory")
#define CP_WAIT1()  asm volatile("cp.async.wait_group 1;" ::: "memory")
#define CP_WAIT2()  asm volatile("cp.async.wait_group 2;" ::: "memory")

__device__ __forceinline__ void ldm_x4(uint32_t* r, uint32_t addr) {
    asm volatile("ldmatrix.sync.aligned.m8n8.x4.shared.b16 {%0,%1,%2,%3}, [%4];"
                 : "=r"(r[0]), "=r"(r[1]), "=r"(r[2]), "=r"(r[3]) : "r"(addr));
}
__device__ __forceinline__ void ldm_x4_t(uint32_t* r, uint32_t addr) {
    asm volatile("ldmatrix.sync.aligned.m8n8.x4.trans.shared.b16 {%0,%1,%2,%3}, [%4];"
                 : "=r"(r[0]), "=r"(r[1]), "=r"(r[2]), "=r"(r[3]) : "r"(addr));
}

__device__ __forceinline__ void mma_f16(float* d, const uint32_t* a, const uint32_t* b) {
    asm volatile(
        "mma.sync.aligned.m16n8k16.row.col.f32.f16.f16.f32 "
        "{%0,%1,%2,%3}, {%4,%5,%6,%7}, {%8,%9}, {%0,%1,%2,%3};"
        : "+f"(d[0]), "+f"(d[1]), "+f"(d[2]), "+f"(d[3])
        : "r"(a[0]), "r"(a[1]), "r"(a[2]), "r"(a[3]), "r"(b[0]), "r"(b[1]));
}

__device__ __forceinline__ float ex2(float x) {
    float r; asm("ex2.approx.f32 %0, %1;" : "=f"(r) : "f"(x)); return r;
}
__device__ __forceinline__ float frcp(float x) {
    float r; asm("rcp.approx.f32 %0, %1;" : "=f"(r) : "f"(x)); return r;
}

__device__ __forceinline__ uint32_t pack_f16(float a, float b) {
    uint32_t r; asm("cvt.rn.f16x2.f32 %0, %1, %2;" : "=r"(r) : "f"(b), "f"(a));
    return r;
}
__device__ __forceinline__ void split2h(float a, float b, uint32_t& hi, uint32_t& lo) {
    hi = pack_f16(a, b);
    __half2 h = *(__half2*)&hi;
    const float la = a - __half2float(h.x);
    const float lb = b - __half2float(h.y);
    lo = pack_f16(la, lb);
}

// ---------------------------------------------------------------------------
// input split: fp32 -> fp16 single (z selects q/k/v)
// ---------------------------------------------------------------------------
__global__ void __launch_bounds__(256) split_in(
    const float4* __restrict__ q, const float4* __restrict__ k,
    const float4* __restrict__ v)
{
    const int z = blockIdx.z;
    const size_t XN4 = (size_t)ROWS * DM / 4;
    const float4* src = (z == 0) ? q : (z == 1) ? k : v;
    uint32_t* fp = (uint32_t*)(g_xf[z]);
    const size_t i = blockIdx.x * 256 + threadIdx.x;
    if (i >= XN4) return;
    float4 vv = src[i];
    fp[2*i]   = pack_f16(vv.x, vv.y);
    fp[2*i+1] = pack_f16(vv.z, vv.w);
}

// weight split: all four weights -> fp16 hi/lo
__global__ void __launch_bounds__(256) split_w(
    const float4* __restrict__ wq, const float4* __restrict__ wk,
    const float4* __restrict__ wv, const float4* __restrict__ wo)
{
    const int z = blockIdx.z;
    const size_t WN4 = (size_t)DM * DM / 4;
    const float4* src = (z == 0) ? wq : (z == 1) ? wk : (z == 2) ? wv : wo;
    uint32_t* hp = (uint32_t*)(g_wfh[z]);
    uint32_t* lp = (uint32_t*)(g_wfl[z]);
    const size_t i = blockIdx.x * 256 + threadIdx.x;
    if (i >= WN4) return;
    float4 vv = src[i];
    uint32_t h0, l0, h1, l1;
    split2h(vv.x, vv.y, h0, l0);
    split2h(vv.z, vv.w, h1, l1);
    hp[2*i] = h0; hp[2*i+1] = h1;
    lp[2*i] = l0; lp[2*i+1] = l1;
}

// ---------------------------------------------------------------------------
// fp16 2-term GEMM: C = A_f16 * (Wh + Wl)^T + bias.
// CTA 128x128, BK=32, 3-STAGE pipeline (wait_group 1 — two loads always in
// flight, stage boundary exposes ~sync only), 8 warps, 2 CTAs/SM.
// MODE 0: fp32 C row-major; MODE 4: fp16 single QKV scatter.
// ---------------------------------------------------------------------------
#define GSTRIDE 40                            // 32 + 8 pad (fp16 elems)
#define ARR_BYTES (128 * GSTRIDE * 2)         // 10240 B per 128x32 array
#define NSTAGE (DM / 32)                      // 32
#define G16_STAGE (3 * ARR_BYTES)             // 30720 B
#define G16_SMEM  (3 * G16_STAGE)             // 92160 B (3 stages)

template<int MODE>
__device__ __forceinline__ void gemm16_body(
    const __half* __restrict__ A, const __half* __restrict__ Bh,
    const __half* __restrict__ Bl, const float* __restrict__ bias,
    float* __restrict__ C, void* __restrict__ Ch, float oscale)
{
    extern __shared__ __align__(128) char smraw[];
    const uint32_t smem0 = smem_u32(smraw);

    const int tid = threadIdx.x;
    const int lane = tid & 31;
    const int wid = tid >> 5;
    const int wm = wid >> 2;
    const int wn = wid & 3;

    const int m0 = blockIdx.y << 7;
    const int n0 = blockIdx.x << 7;

    const __half* gsrc[3] = {
        A + (size_t)m0 * DM, Bh + (size_t)n0 * DM, Bl + (size_t)n0 * DM
    };

    const int r0c = tid >> 2, cc0 = tid & 3;   // 128x32 fp16: 2 chunks/thread/array
    const int r1c = r0c + 64;

    auto load_stage = [&](int s) {
        const int kk = s * 32;
        const uint32_t sb = smem0 + (s % 3) * G16_STAGE;
        #pragma unroll
        for (int a = 0; a < 3; a++) {
            const __half* g = gsrc[a];
            const uint32_t ab = sb + a * ARR_BYTES;
            CP_ASYNC16(ab + r0c * (GSTRIDE*2) + cc0 * 16,
                       g + (size_t)r0c * DM + kk + cc0 * 8);
            CP_ASYNC16(ab + r1c * (GSTRIDE*2) + cc0 * 16,
                       g + (size_t)r1c * DM + kk + cc0 * 8);
        }
    };

    float acc[4][4][4];
    #pragma unroll
    for (int i = 0; i < 4; i++)
        #pragma unroll
        for (int j = 0; j < 4; j++)
            #pragma unroll
            for (int e = 0; e < 4; e++) acc[i][j][e] = 0.f;

    const int a_r = lane & 15, a_c = (lane >> 4) << 3;
    const int b_r = (lane & 7) + (((lane >> 3) & 2) << 2);
    const int b_c = ((lane >> 3) & 1) << 3;

    load_stage(0); CP_COMMIT();
    load_stage(1); CP_COMMIT();

    for (int s = 0; s < NSTAGE; s++) {
        CP_WAIT1();                      // stage s landed; s+1 may be pending
        __syncthreads();                 // buffer (s+2)%3 free to overwrite
        if (s + 2 < NSTAGE) load_stage(s + 2);
        CP_COMMIT();                     // empty group near drain keeps count exact

        const uint32_t sb = smem0 + (s % 3) * G16_STAGE;
        const uint32_t sA  = sb;
        const uint32_t sBh = sb + ARR_BYTES;
        const uint32_t sBl = sb + 2 * ARR_BYTES;

        #pragma unroll
        for (int k16 = 0; k16 < 2; k16++) {
            const int kc = k16 * 16;
            uint32_t bh[2][4], bl[2][4];
            #pragma unroll
            for (int np = 0; np < 2; np++) {
                const uint32_t off =
                    ((wn * 32 + np * 16 + b_r) * GSTRIDE + kc + b_c) * 2;
                ldm_x4(bh[np], sBh + off);
                ldm_x4(bl[np], sBl + off);
            }
            #pragma unroll
            for (int mt = 0; mt < 4; mt++) {
                uint32_t af[4];
                const uint32_t off =
                    ((wm * 64 + mt * 16 + a_r) * GSTRIDE + kc + a_c) * 2;
                ldm_x4(af, sA + off);
                #pragma unroll
                for (int nt = 0; nt < 4; nt++)
                    mma_f16(acc[mt][nt], af, &bh[nt >> 1][(nt & 1) * 2]);
                #pragma unroll
                for (int nt = 0; nt < 4; nt++)
                    mma_f16(acc[mt][nt], af, &bl[nt >> 1][(nt & 1) * 2]);
            }
        }
    }

    #pragma unroll
    for (int mt = 0; mt < 4; mt++) {
        #pragma unroll
        for (int nt = 0; nt < 4; nt++) {
            const int col = n0 + wn * 32 + nt * 8 + ((lane & 3) << 1);
            const float b0 = bias[col], b1 = bias[col + 1];
            #pragma unroll
            for (int half = 0; half < 2; half++) {
                const int row = m0 + wm * 64 + mt * 16 + (lane >> 2) + half * 8;
                const float vx = (acc[mt][nt][half * 2 + 0] + b0) * oscale;
                const float vy = (acc[mt][nt][half * 2 + 1] + b1) * oscale;
                if (MODE == 0) {
                    float2 vo; vo.x = vx; vo.y = vy;
                    *(float2*)&C[(size_t)row * DM + col] = vo;
                } else {
                    const int h = col >> 6, d = col & 63;
                    const int nb = row >> 11, kq = row & 2047;
                    const size_t idx = (((size_t)(h * NB + nb)) * SEQ + kq) * HD + d;
                    *(uint32_t*)&((__half*)Ch)[idx] = pack_f16(vx, vy);
                }
            }
        }
    }
}

__global__ void __launch_bounds__(256, 2) gemm_qkv16(
    const float* __restrict__ bq, const float* __restrict__ bk,
    const float* __restrict__ bv)
{
    const int z = blockIdx.z;
    if (z == 0) {
        gemm16_body<4>(g_xf[0], g_wfh[0], g_wfl[0], bq, nullptr, g_qf, QSCALE);
    } else if (z == 1) {
        gemm16_body<4>(g_xf[1], g_wfh[1], g_wfl[1], bk, nullptr, g_kf, 1.f);
    } else {
        gemm16_body<4>(g_xf[2], g_wfh[2], g_wfl[2], bv, nullptr, g_vf, 1.f);
    }
}

__global__ void __launch_bounds__(256, 2) gemm_out16(
    const float* __restrict__ bo, float* __restrict__ C)
{
    gemm16_body<0>(g_yf, g_wfh[3], g_wfl[3], bo, C, nullptr, 1.f);
}

// ---------------------------------------------------------------------------
// FA2-style HMMA attention, 2 CTAs/SM, all-fp16, software-pipelined
// (unchanged from round 15: S 1-term, PV 1-term, 4 KV buffers, depth 2).
// smem: [Qf 18432][4 x (K 9216 | V 9216)] = 92160 B.
// ---------------------------------------------------------------------------
#define ASTRIDE 72
#define AARR    (64 * ASTRIDE * 2)          // 9216 B
#define ASTAGE  (2 * AARR)                  // 18432 B (K + V)
#define QONE    (128 * ASTRIDE * 2)         // 18432 B

__global__ void __launch_bounds__(256, 2) attn_mma(
    const __half* __restrict__ Qf_, const __half* __restrict__ Kf_,
    const __half* __restrict__ Vf_, __half* __restrict__ Yf)
{
    extern __shared__ __align__(128) char smraw[];
    const uint32_t s0 = smem_u32(smraw);
    const uint32_t stg = s0 + QONE;

    const int tid = threadIdx.x;
    const int lane = tid & 31;
    const int wid = tid >> 5;
    const int hn = blockIdx.y;
    const int h = hn >> 1, n = hn & 1;
    const int q0 = blockIdx.x << 7;
    const size_t hoff = (size_t)hn * SEQ * HD;

    const int a_r = lane & 15, a_c = (lane >> 4) << 3;
    const int b_r = (lane & 7) + (((lane >> 3) & 2) << 2);
    const int b_c = ((lane >> 3) & 1) << 3;

    {
        const __half* Qg = Qf_ + hoff + (size_t)q0 * HD;
        #pragma unroll
        for (int c = 0; c < 4; c++) {
            const int ch = tid + c * 256;
            const int row = ch >> 3, c16 = ch & 7;
            CP_ASYNC16(s0 + row * 144 + c16 * 16, Qg + row * 64 + c16 * 8);
        }
        CP_COMMIT();
    }

    const char* gsK = (const char*)(Kf_ + hoff);
    const char* gsV = (const char*)(Vf_ + hoff);

    auto load_stage = [&](int buf, int src) {
        const int kv0 = src << 6;
        const uint32_t sb = stg + buf * ASTAGE;
        const char* gs[2] = { gsK, gsV };
        #pragma unroll
        for (int a = 0; a < 2; a++) {
            #pragma unroll
            for (int c = 0; c < 2; c++) {
                const int ch = tid + c * 256;
                const int row = ch >> 3, c16 = ch & 7;
                CP_ASYNC16(sb + a * AARR + row * 144 + c16 * 16,
                           gs[a] + (size_t)(kv0 + row) * 128 + c16 * 16);
            }
        }
    };

    load_stage(0, 0); CP_COMMIT();
    load_stage(1, 1); CP_COMMIT();

    CP_WAIT2();
    __syncthreads();
    uint32_t qf[4][4];
    const uint32_t qbase = ((wid * 16 + a_r) * ASTRIDE + a_c) * 2;
    #pragma unroll
    for (int t4 = 0; t4 < 4; t4++)
        ldm_x4(qf[t4], s0 + qbase + t4 * 32);

    float m0r = -1e30f, m1r = -1e30f, l0 = 0.f, l1 = 0.f;
    float O[8][4];
    #pragma unroll
    for (int j = 0; j < 8; j++)
        #pragma unroll
        for (int e = 0; e < 4; e++) O[j][e] = 0.f;
    uint32_t pa[4][4];

    for (int t = 0; t < SEQ / 64; t++) {
        CP_WAIT1();
        __syncthreads();
        {
            const int src = (t + 2 < SEQ / 64) ? t + 2 : SEQ / 64 - 1;
            load_stage((t + 2) & 3, src);
            CP_COMMIT();
        }

        const uint32_t sb = stg + (t & 3) * ASTAGE;

        float S[8][4];
        #pragma unroll
        for (int j = 0; j < 8; j++)
            #pragma unroll
            for (int e = 0; e < 4; e++) S[j][e] = 0.f;

        #pragma unroll
        for (int t4 = 0; t4 < 4; t4++) {
            #pragma unroll
            for (int jp = 0; jp < 4; jp++) {
                uint32_t kf[4];
                const uint32_t off = ((16 * jp + b_r) * ASTRIDE + 16 * t4 + b_c) * 2;
                ldm_x4(kf, sb + off);
                mma_f16(S[2*jp],   qf[t4], &kf[0]);
                mma_f16(S[2*jp+1], qf[t4], &kf[2]);
            }
        }

        if (t > 0) {
            const uint32_t sbv = stg + ((t - 1) & 3) * ASTAGE + AARR;
            #pragma unroll
            for (int t4 = 0; t4 < 4; t4++) {
                #pragma unroll
                for (int jp = 0; jp < 4; jp++) {
                    uint32_t vf[4];
                    const uint32_t off =
                        ((16 * t4 + (lane & 15)) * ASTRIDE + 16 * jp + a_c) * 2;
                    ldm_x4_t(vf, sbv + off);
                    mma_f16(O[2*jp],   pa[t4], &vf[0]);
                    mma_f16(O[2*jp+1], pa[t4], &vf[2]);
                }
            }
        }

        float corr0, corr1;
        {
            float tm = S[0][0];
            #pragma unroll
            for (int j = 0; j < 8; j++) tm = fmaxf(tm, fmaxf(S[j][0], S[j][1]));
            tm = fmaxf(tm, __shfl_xor_sync(0xffffffffu, tm, 1));
            tm = fmaxf(tm, __shfl_xor_sync(0xffffffffu, tm, 2));
            const float mnew = fmaxf(m0r, tm);
            corr0 = ex2(m0r - mnew);
            float rs = 0.f;
            #pragma unroll
            for (int j = 0; j < 8; j++) {
                S[j][0] = ex2(S[j][0] - mnew);
                S[j][1] = ex2(S[j][1] - mnew);
                rs += S[j][0] + S[j][1];
            }
            rs += __shfl_xor_sync(0xffffffffu, rs, 1);
            rs += __shfl_xor_sync(0xffffffffu, rs, 2);
            l0 = l0 * corr0 + rs;
            m0r = mnew;
        }
        {
            float tm = S[0][2];
            #pragma unroll
            for (int j = 0; j < 8; j++) tm = fmaxf(tm, fmaxf(S[j][2], S[j][3]));
            tm = fmaxf(tm, __shfl_xor_sync(0xffffffffu, tm, 1));
            tm = fmaxf(tm, __shfl_xor_sync(0xffffffffu, tm, 2));
            const float mnew = fmaxf(m1r, tm);
            corr1 = ex2(m1r - mnew);
            float rs = 0.f;
            #pragma unroll
            for (int j = 0; j < 8; j++) {
                S[j][2] = ex2(S[j][2] - mnew);
                S[j][3] = ex2(S[j][3] - mnew);
                rs += S[j][2] + S[j][3];
            }
            rs += __shfl_xor_sync(0xffffffffu, rs, 1);
            rs += __shfl_xor_sync(0xffffffffu, rs, 2);
            l1 = l1 * corr1 + rs;
            m1r = mnew;
        }

        #pragma unroll
        for (int j = 0; j < 8; j++) {
            O[j][0] *= corr0; O[j][1] *= corr0;
            O[j][2] *= corr1; O[j][3] *= corr1;
        }
        #pragma unroll
        for (int t4 = 0; t4 < 4; t4++) {
            pa[t4][0] = pack_f16(S[2*t4][0],   S[2*t4][1]);
            pa[t4][1] = pack_f16(S[2*t4][2],   S[2*t4][3]);
            pa[t4][2] = pack_f16(S[2*t4+1][0], S[2*t4+1][1]);
            pa[t4][3] = pack_f16(S[2*t4+1][2], S[2*t4+1][3]);
        }
    }

    {
        const uint32_t sbv = stg + ((SEQ / 64 - 1) & 3) * ASTAGE + AARR;
        #pragma unroll
        for (int t4 = 0; t4 < 4; t4++) {
            #pragma unroll
            for (int jp = 0; jp < 4; jp++) {
                uint32_t vf[4];
                const uint32_t off =
                    ((16 * t4 + (lane & 15)) * ASTRIDE + 16 * jp + a_c) * 2;
                ldm_x4_t(vf, sbv + off);
                mma_f16(O[2*jp],   pa[t4], &vf[0]);
                mma_f16(O[2*jp+1], pa[t4], &vf[2]);
            }
        }
    }

    const float inv0 = frcp(l0), inv1 = frcp(l1);
    #pragma unroll
    for (int j = 0; j < 8; j++) {
        const int col = h * 64 + 8 * j + ((lane & 3) << 1);
        #pragma unroll
        for (int half = 0; half < 2; half++) {
            const int row = q0 + wid * 16 + (lane >> 2) + half * 8;
            const float inv = half ? inv1 : inv0;
            const float y0 = O[j][half * 2 + 0] * inv;
            const float y1 = O[j][half * 2 + 1] * inv;
            const size_t idx = ((size_t)(n * SEQ) + row) * DM + col;
            *(uint32_t*)&Yf[idx] = pack_f16(y0, y1);
        }
    }
}

// ---------------------------------------------------------------------------
extern "C" void kernel_launch(void* const* d_in, const int* in_sizes, int n_in,
                              void* d_out, int out_size)
{
    const float* q  = (const float*)d_in[0];
    const float* k  = (const float*)d_in[1];
    const float* v  = (const float*)d_in[2];
    const float* Wq = (const float*)d_in[3];
    const float* bq = (const float*)d_in[4];
    const float* Wk = (const float*)d_in[5];
    const float* bk = (const float*)d_in[6];
    const float* Wv = (const float*)d_in[7];
    const float* bv = (const float*)d_in[8];
    const float* Wo = (const float*)d_in[9];
    const float* bo = (const float*)d_in[10];
    float* out = (float*)d_out;

    __half *qf, *kf, *vf, *yf;
    cudaGetSymbolAddress((void**)&qf, g_qf);
    cudaGetSymbolAddress((void**)&kf, g_kf);
    cudaGetSymbolAddress((void**)&vf, g_vf);
    cudaGetSymbolAddress((void**)&yf, g_yf);

    const size_t XN = (size_t)ROWS * DM;
    const size_t WN = (size_t)DM * DM;

    { const dim3 gi((unsigned)(XN/4/256), 1, 3);
      split_in<<<gi, 256>>>((const float4*)q, (const float4*)k, (const float4*)v); }
    { const dim3 gw((unsigned)(WN/4/256), 1, 4);
      split_w<<<gw, 256>>>((const float4*)Wq, (const float4*)Wk,
                           (const float4*)Wv, (const float4*)Wo); }

    cudaFuncSetAttribute((const void*)gemm_qkv16,
                         cudaFuncAttributeMaxDynamicSharedMemorySize, G16_SMEM);
    cudaFuncSetAttribute((const void*)gemm_out16,
                         cudaFuncAttributeMaxDynamicSharedMemorySize, G16_SMEM);
    const dim3 gq(DM/128, ROWS/128, 3);
    gemm_qkv16<<<gq, 256, G16_SMEM>>>(bq, bk, bv);

    const int asmem = QONE + 4 * ASTAGE;   // 92160
    cudaFuncSetAttribute((const void*)attn_mma,
                         cudaFuncAttributeMaxDynamicSharedMemorySize, asmem);
    const dim3 ga(SEQ/128, NH*NB);  // (16, 32)
    attn_mma<<<ga, 256, asmem>>>(qf, kf, vf, yf);

    const dim3 gg(DM/128, ROWS/128);
    gemm_out16<<<gg, 256, G16_SMEM>>>(bo, out);
}

// round 17
// speedup vs baseline: 1.2160x; 1.2160x over previous
#include <cuda_runtime.h>
#include <cuda_bf16.h>
#include <cuda_fp16.h>
#include <cstdint>

#define NB   2
#define SEQ  2048
#define DM   1024
#define NH   16
#define HD   64
#define ROWS (NB*SEQ)          // 4096
// softmax scale 1/sqrt(64) folded into Q projection together with log2(e):
#define QSCALE 0.18033688011112042f   // 0.125 * log2(e)

// ---------------------------------------------------------------------------
// Scratch (allocation-free: __device__ globals)
// ---------------------------------------------------------------------------
#define PROJN ((size_t)NH*NB*SEQ*HD)     // 4M elems
__device__ __align__(256) __half g_qf[PROJN];                       // fp16 Q
__device__ __align__(256) __half g_kf[PROJN];                       // fp16 K
__device__ __align__(256) __half g_vf[PROJN];                       // fp16 V
__device__ __align__(256) __half g_xf[3][(size_t)ROWS*DM];          // fp16 inputs
__device__ __align__(256) __half g_wfh[4][(size_t)DM*DM];           // fp16 W hi
__device__ __align__(256) __half g_wfl[4][(size_t)DM*DM];           // fp16 W lo
__device__ __align__(256) __half g_yf[(size_t)ROWS*DM];             // fp16 Y

// ---------------------------------------------------------------------------
// PTX helpers (baseline sm_80+ features: mma.sync / ldmatrix / cp.async)
// ---------------------------------------------------------------------------
__device__ __forceinline__ uint32_t smem_u32(const void* p) {
    uint32_t a;
    asm("{ .reg .u64 t; cvta.to.shared.u64 t, %1; cvt.u32.u64 %0, t; }"
        : "=r"(a) : "l"(p));
    return a;
}

#define CP_ASYNC16(dst, src) \
    asm volatile("cp.async.cg.shared.global [%0], [%1], 16;" :: "r"(dst), "l"(src))
#define CP_COMMIT() asm volatile("cp.async.commit_group;" ::: "memory")
#define CP_WAIT0()  asm volatile("cp.async.wait_group 0;" ::: "memory")
#define CP_WAIT1()  asm volatile("cp.async.wait_group 1;" ::: "memory")
#define CP_WAIT2()  asm volatile("cp.async.wait_group 2;" ::: "memory")

__device__ __forceinline__ void ldm_x4(uint32_t* r, uint32_t addr) {
    asm volatile("ldmatrix.sync.aligned.m8n8.x4.shared.b16 {%0,%1,%2,%3}, [%4];"
                 : "=r"(r[0]), "=r"(r[1]), "=r"(r[2]), "=r"(r[3]) : "r"(addr));
}
__device__ __forceinline__ void ldm_x4_t(uint32_t* r, uint32_t addr) {
    asm volatile("ldmatrix.sync.aligned.m8n8.x4.trans.shared.b16 {%0,%1,%2,%3}, [%4];"
                 : "=r"(r[0]), "=r"(r[1]), "=r"(r[2]), "=r"(r[3]) : "r"(addr));
}

__device__ __forceinline__ void mma_f16(float* d, const uint32_t* a, const uint32_t* b) {
    asm volatile(
        "mma.sync.aligned.m16n8k16.row.col.f32.f16.f16.f32 "
        "{%0,%1,%2,%3}, {%4,%5,%6,%7}, {%8,%9}, {%0,%1,%2,%3};"
        : "+f"(d[0]), "+f"(d[1]), "+f"(d[2]), "+f"(d[3])
        : "r"(a[0]), "r"(a[1]), "r"(a[2]), "r"(a[3]), "r"(b[0]), "r"(b[1]));
}

__device__ __forceinline__ float ex2(float x) {
    float r; asm("ex2.approx.f32 %0, %1;" : "=f"(r) : "f"(x)); return r;
}
__device__ __forceinline__ float frcp(float x) {
    float r; asm("rcp.approx.f32 %0, %1;" : "=f"(r) : "f"(x)); return r;
}

__device__ __forceinline__ uint32_t pack_f16(float a, float b) {
    uint32_t r; asm("cvt.rn.f16x2.f32 %0, %1, %2;" : "=r"(r) : "f"(b), "f"(a));
    return r;
}
__device__ __forceinline__ void split2h(float a, float b, uint32_t& hi, uint32_t& lo) {
    hi = pack_f16(a, b);
    __half2 h = *(__half2*)&hi;
    const float la = a - __half2float(h.x);
    const float lb = b - __half2float(h.y);
    lo = pack_f16(la, lb);
}

// ---------------------------------------------------------------------------
// input split: fp32 -> fp16 single (z selects q/k/v)
// ---------------------------------------------------------------------------
__global__ void __launch_bounds__(256) split_in(
    const float4* __restrict__ q, const float4* __restrict__ k,
    const float4* __restrict__ v)
{
    const int z = blockIdx.z;
    const size_t XN4 = (size_t)ROWS * DM / 4;
    const float4* src = (z == 0) ? q : (z == 1) ? k : v;
    uint32_t* fp = (uint32_t*)(g_xf[z]);
    const size_t i = blockIdx.x * 256 + threadIdx.x;
    if (i >= XN4) return;
    float4 vv = src[i];
    fp[2*i]   = pack_f16(vv.x, vv.y);
    fp[2*i+1] = pack_f16(vv.z, vv.w);
}

// weight split: all four weights -> fp16 hi/lo (lo unused for Wq/Wk)
__global__ void __launch_bounds__(256) split_w(
    const float4* __restrict__ wq, const float4* __restrict__ wk,
    const float4* __restrict__ wv, const float4* __restrict__ wo)
{
    const int z = blockIdx.z;
    const size_t WN4 = (size_t)DM * DM / 4;
    const float4* src = (z == 0) ? wq : (z == 1) ? wk : (z == 2) ? wv : wo;
    uint32_t* hp = (uint32_t*)(g_wfh[z]);
    uint32_t* lp = (uint32_t*)(g_wfl[z]);
    const size_t i = blockIdx.x * 256 + threadIdx.x;
    if (i >= WN4) return;
    float4 vv = src[i];
    uint32_t h0, l0, h1, l1;
    split2h(vv.x, vv.y, h0, l0);
    split2h(vv.z, vv.w, h1, l1);
    hp[2*i] = h0; hp[2*i+1] = h1;
    lp[2*i] = l0; lp[2*i+1] = l1;
}

// ---------------------------------------------------------------------------
// fp16 GEMM: C = A_f16 * (Wh [+ Wl])^T + bias.
// CTA 128x128, BK=64 (16 stages), 8 warps, DOUBLE-buffered wait0 (round-15
// config: BK=64 compute/stage >> load latency, so deeper staging regressed).
// TT (two-term): true  -> stage {A, Bh, Bl}, 2 MMA sets  (V, Wo)
//                false -> stage {A, Bh},     1 MMA set   (Q, K — attenuated)
// MODE 0: fp32 C row-major; MODE 4: fp16 single QKV scatter.
// ---------------------------------------------------------------------------
#define GSTRIDE 72                            // 64 + 8 pad (fp16 elems)
#define ARR_BYTES (128 * GSTRIDE * 2)         // 18432 B per 128x64 array
#define NSTAGE (DM / 64)                      // 16
#define G16_SMEM (2 * 3 * ARR_BYTES)          // 110592 B (max: 2 stages x 3 arrays)

template<int MODE, bool TT>
__device__ __forceinline__ void gemm16_body(
    const __half* __restrict__ A, const __half* __restrict__ Bh,
    const __half* __restrict__ Bl, const float* __restrict__ bias,
    float* __restrict__ C, void* __restrict__ Ch, float oscale)
{
    extern __shared__ __align__(128) char smraw[];
    const uint32_t smem0 = smem_u32(smraw);
    const int NARR = TT ? 3 : 2;
    const uint32_t STAGE = NARR * ARR_BYTES;

    const int tid = threadIdx.x;
    const int lane = tid & 31;
    const int wid = tid >> 5;
    const int wm = wid >> 2;
    const int wn = wid & 3;

    const int m0 = blockIdx.y << 7;
    const int n0 = blockIdx.x << 7;

    const __half* gsrc[3] = {
        A + (size_t)m0 * DM, Bh + (size_t)n0 * DM,
        TT ? (Bl + (size_t)n0 * DM) : nullptr
    };

    auto load_stage = [&](int s) {
        const int kk = s * 64;
        const uint32_t sb = smem0 + (s & 1) * STAGE;
        #pragma unroll
        for (int a = 0; a < NARR; a++) {
            const __half* g = gsrc[a];
            const uint32_t ab = sb + a * ARR_BYTES;
            #pragma unroll
            for (int c = 0; c < 4; c++) {
                const int ch = tid + c * 256;
                const int row = ch >> 3, c16 = ch & 7;
                CP_ASYNC16(ab + row * (GSTRIDE*2) + c16 * 16,
                           g + (size_t)row * DM + kk + c16 * 8);
            }
        }
    };

    float acc[4][4][4];
    #pragma unroll
    for (int i = 0; i < 4; i++)
        #pragma unroll
        for (int j = 0; j < 4; j++)
            #pragma unroll
            for (int e = 0; e < 4; e++) acc[i][j][e] = 0.f;

    const int a_r = lane & 15, a_c = (lane >> 4) << 3;
    const int b_r = (lane & 7) + (((lane >> 3) & 2) << 2);
    const int b_c = ((lane >> 3) & 1) << 3;

    load_stage(0);
    CP_COMMIT();

    for (int s = 0; s < NSTAGE; s++) {
        CP_WAIT0();
        __syncthreads();
        if (s + 1 < NSTAGE) { load_stage(s + 1); CP_COMMIT(); }

        const uint32_t sb = smem0 + (s & 1) * STAGE;
        const uint32_t sA  = sb;
        const uint32_t sBh = sb + ARR_BYTES;
        const uint32_t sBl = sb + 2 * ARR_BYTES;

        #pragma unroll
        for (int k16 = 0; k16 < 4; k16++) {
            const int kc = k16 * 16;
            uint32_t bh[2][4], bl[2][4];
            #pragma unroll
            for (int np = 0; np < 2; np++) {
                const uint32_t off =
                    ((wn * 32 + np * 16 + b_r) * GSTRIDE + kc + b_c) * 2;
                ldm_x4(bh[np], sBh + off);
                if (TT) ldm_x4(bl[np], sBl + off);
            }
            #pragma unroll
            for (int mt = 0; mt < 4; mt++) {
                uint32_t af[4];
                const uint32_t off =
                    ((wm * 64 + mt * 16 + a_r) * GSTRIDE + kc + a_c) * 2;
                ldm_x4(af, sA + off);
                #pragma unroll
                for (int nt = 0; nt < 4; nt++)
                    mma_f16(acc[mt][nt], af, &bh[nt >> 1][(nt & 1) * 2]);
                if (TT) {
                    #pragma unroll
                    for (int nt = 0; nt < 4; nt++)
                        mma_f16(acc[mt][nt], af, &bl[nt >> 1][(nt & 1) * 2]);
                }
            }
        }
    }

    #pragma unroll
    for (int mt = 0; mt < 4; mt++) {
        #pragma unroll
        for (int nt = 0; nt < 4; nt++) {
            const int col = n0 + wn * 32 + nt * 8 + ((lane & 3) << 1);
            const float b0 = bias[col], b1 = bias[col + 1];
            #pragma unroll
            for (int half = 0; half < 2; half++) {
                const int row = m0 + wm * 64 + mt * 16 + (lane >> 2) + half * 8;
                const float vx = (acc[mt][nt][half * 2 + 0] + b0) * oscale;
                const float vy = (acc[mt][nt][half * 2 + 1] + b1) * oscale;
                if (MODE == 0) {
                    float2 vo; vo.x = vx; vo.y = vy;
                    *(float2*)&C[(size_t)row * DM + col] = vo;
                } else {
                    const int h = col >> 6, d = col & 63;
                    const int nb = row >> 11, kq = row & 2047;
                    const size_t idx = (((size_t)(h * NB + nb)) * SEQ + kq) * HD + d;
                    *(uint32_t*)&((__half*)Ch)[idx] = pack_f16(vx, vy);
                }
            }
        }
    }
}

__global__ void __launch_bounds__(256, 2) gemm_qkv16(
    const float* __restrict__ bq, const float* __restrict__ bk,
    const float* __restrict__ bv)
{
    const int z = blockIdx.z;
    if (z == 0) {
        gemm16_body<4, false>(g_xf[0], g_wfh[0], nullptr, bq, nullptr, g_qf, QSCALE);
    } else if (z == 1) {
        gemm16_body<4, false>(g_xf[1], g_wfh[1], nullptr, bk, nullptr, g_kf, 1.f);
    } else {
        gemm16_body<4, true>(g_xf[2], g_wfh[2], g_wfl[2], bv, nullptr, g_vf, 1.f);
    }
}

__global__ void __launch_bounds__(256, 2) gemm_out16(
    const float* __restrict__ bo, float* __restrict__ C)
{
    gemm16_body<0, true>(g_yf, g_wfh[3], g_wfl[3], bo, C, nullptr, 1.f);
}

// ---------------------------------------------------------------------------
// FA2-style HMMA attention, 2 CTAs/SM, all-fp16, software-pipelined
// (unchanged from round 15: S 1-term, PV 1-term, 4 KV buffers, depth 2).
// smem: [Qf 18432][4 x (K 9216 | V 9216)] = 92160 B.
// ---------------------------------------------------------------------------
#define ASTRIDE 72
#define AARR    (64 * ASTRIDE * 2)          // 9216 B
#define ASTAGE  (2 * AARR)                  // 18432 B (K + V)
#define QONE    (128 * ASTRIDE * 2)         // 18432 B

__global__ void __launch_bounds__(256, 2) attn_mma(
    const __half* __restrict__ Qf_, const __half* __restrict__ Kf_,
    const __half* __restrict__ Vf_, __half* __restrict__ Yf)
{
    extern __shared__ __align__(128) char smraw[];
    const uint32_t s0 = smem_u32(smraw);
    const uint32_t stg = s0 + QONE;

    const int tid = threadIdx.x;
    const int lane = tid & 31;
    const int wid = tid >> 5;
    const int hn = blockIdx.y;
    const int h = hn >> 1, n = hn & 1;
    const int q0 = blockIdx.x << 7;
    const size_t hoff = (size_t)hn * SEQ * HD;

    const int a_r = lane & 15, a_c = (lane >> 4) << 3;
    const int b_r = (lane & 7) + (((lane >> 3) & 2) << 2);
    const int b_c = ((lane >> 3) & 1) << 3;

    {
        const __half* Qg = Qf_ + hoff + (size_t)q0 * HD;
        #pragma unroll
        for (int c = 0; c < 4; c++) {
            const int ch = tid + c * 256;
            const int row = ch >> 3, c16 = ch & 7;
            CP_ASYNC16(s0 + row * 144 + c16 * 16, Qg + row * 64 + c16 * 8);
        }
        CP_COMMIT();
    }

    const char* gsK = (const char*)(Kf_ + hoff);
    const char* gsV = (const char*)(Vf_ + hoff);

    auto load_stage = [&](int buf, int src) {
        const int kv0 = src << 6;
        const uint32_t sb = stg + buf * ASTAGE;
        const char* gs[2] = { gsK, gsV };
        #pragma unroll
        for (int a = 0; a < 2; a++) {
            #pragma unroll
            for (int c = 0; c < 2; c++) {
                const int ch = tid + c * 256;
                const int row = ch >> 3, c16 = ch & 7;
                CP_ASYNC16(sb + a * AARR + row * 144 + c16 * 16,
                           gs[a] + (size_t)(kv0 + row) * 128 + c16 * 16);
            }
        }
    };

    load_stage(0, 0); CP_COMMIT();
    load_stage(1, 1); CP_COMMIT();

    CP_WAIT2();
    __syncthreads();
    uint32_t qf[4][4];
    const uint32_t qbase = ((wid * 16 + a_r) * ASTRIDE + a_c) * 2;
    #pragma unroll
    for (int t4 = 0; t4 < 4; t4++)
        ldm_x4(qf[t4], s0 + qbase + t4 * 32);

    float m0r = -1e30f, m1r = -1e30f, l0 = 0.f, l1 = 0.f;
    float O[8][4];
    #pragma unroll
    for (int j = 0; j < 8; j++)
        #pragma unroll
        for (int e = 0; e < 4; e++) O[j][e] = 0.f;
    uint32_t pa[4][4];

    for (int t = 0; t < SEQ / 64; t++) {
        CP_WAIT1();
        __syncthreads();
        {
            const int src = (t + 2 < SEQ / 64) ? t + 2 : SEQ / 64 - 1;
            load_stage((t + 2) & 3, src);
            CP_COMMIT();
        }

        const uint32_t sb = stg + (t & 3) * ASTAGE;

        float S[8][4];
        #pragma unroll
        for (int j = 0; j < 8; j++)
            #pragma unroll
            for (int e = 0; e < 4; e++) S[j][e] = 0.f;

        #pragma unroll
        for (int t4 = 0; t4 < 4; t4++) {
            #pragma unroll
            for (int jp = 0; jp < 4; jp++) {
                uint32_t kf[4];
                const uint32_t off = ((16 * jp + b_r) * ASTRIDE + 16 * t4 + b_c) * 2;
                ldm_x4(kf, sb + off);
                mma_f16(S[2*jp],   qf[t4], &kf[0]);
                mma_f16(S[2*jp+1], qf[t4], &kf[2]);
            }
        }

        if (t > 0) {
            const uint32_t sbv = stg + ((t - 1) & 3) * ASTAGE + AARR;
            #pragma unroll
            for (int t4 = 0; t4 < 4; t4++) {
                #pragma unroll
                for (int jp = 0; jp < 4; jp++) {
                    uint32_t vf[4];
                    const uint32_t off =
                        ((16 * t4 + (lane & 15)) * ASTRIDE + 16 * jp + a_c) * 2;
                    ldm_x4_t(vf, sbv + off);
                    mma_f16(O[2*jp],   pa[t4], &vf[0]);
                    mma_f16(O[2*jp+1], pa[t4], &vf[2]);
                }
            }
        }

        float corr0, corr1;
        {
            float tm = S[0][0];
            #pragma unroll
            for (int j = 0; j < 8; j++) tm = fmaxf(tm, fmaxf(S[j][0], S[j][1]));
            tm = fmaxf(tm, __shfl_xor_sync(0xffffffffu, tm, 1));
            tm = fmaxf(tm, __shfl_xor_sync(0xffffffffu, tm, 2));
            const float mnew = fmaxf(m0r, tm);
            corr0 = ex2(m0r - mnew);
            float rs = 0.f;
            #pragma unroll
            for (int j = 0; j < 8; j++) {
                S[j][0] = ex2(S[j][0] - mnew);
                S[j][1] = ex2(S[j][1] - mnew);
                rs += S[j][0] + S[j][1];
            }
            rs += __shfl_xor_sync(0xffffffffu, rs, 1);
            rs += __shfl_xor_sync(0xffffffffu, rs, 2);
            l0 = l0 * corr0 + rs;
            m0r = mnew;
        }
        {
            float tm = S[0][2];
            #pragma unroll
            for (int j = 0; j < 8; j++) tm = fmaxf(tm, fmaxf(S[j][2], S[j][3]));
            tm = fmaxf(tm, __shfl_xor_sync(0xffffffffu, tm, 1));
            tm = fmaxf(tm, __shfl_xor_sync(0xffffffffu, tm, 2));
            const float mnew = fmaxf(m1r, tm);
            corr1 = ex2(m1r - mnew);
            float rs = 0.f;
            #pragma unroll
            for (int j = 0; j < 8; j++) {
                S[j][2] = ex2(S[j][2] - mnew);
                S[j][3] = ex2(S[j][3] - mnew);
                rs += S[j][2] + S[j][3];
            }
            rs += __shfl_xor_sync(0xffffffffu, rs, 1);
            rs += __shfl_xor_sync(0xffffffffu, rs, 2);
            l1 = l1 * corr1 + rs;
            m1r = mnew;
        }

        #pragma unroll
        for (int j = 0; j < 8; j++) {
            O[j][0] *= corr0; O[j][1] *= corr0;
            O[j][2] *= corr1; O[j][3] *= corr1;
        }
        #pragma unroll
        for (int t4 = 0; t4 < 4; t4++) {
            pa[t4][0] = pack_f16(S[2*t4][0],   S[2*t4][1]);
            pa[t4][1] = pack_f16(S[2*t4][2],   S[2*t4][3]);
            pa[t4][2] = pack_f16(S[2*t4+1][0], S[2*t4+1][1]);
            pa[t4][3] = pack_f16(S[2*t4+1][2], S[2*t4+1][3]);
        }
    }

    {
        const uint32_t sbv = stg + ((SEQ / 64 - 1) & 3) * ASTAGE + AARR;
        #pragma unroll
        for (int t4 = 0; t4 < 4; t4++) {
            #pragma unroll
            for (int jp = 0; jp < 4; jp++) {
                uint32_t vf[4];
                const uint32_t off =
                    ((16 * t4 + (lane & 15)) * ASTRIDE + 16 * jp + a_c) * 2;
                ldm_x4_t(vf, sbv + off);
                mma_f16(O[2*jp],   pa[t4], &vf[0]);
                mma_f16(O[2*jp+1], pa[t4], &vf[2]);
            }
        }
    }

    const float inv0 = frcp(l0), inv1 = frcp(l1);
    #pragma unroll
    for (int j = 0; j < 8; j++) {
        const int col = h * 64 + 8 * j + ((lane & 3) << 1);
        #pragma unroll
        for (int half = 0; half < 2; half++) {
            const int row = q0 + wid * 16 + (lane >> 2) + half * 8;
            const float inv = half ? inv1 : inv0;
            const float y0 = O[j][half * 2 + 0] * inv;
            const float y1 = O[j][half * 2 + 1] * inv;
            const size_t idx = ((size_t)(n * SEQ) + row) * DM + col;
            *(uint32_t*)&Yf[idx] = pack_f16(y0, y1);
        }
    }
}

// ---------------------------------------------------------------------------
extern "C" void kernel_launch(void* const* d_in, const int* in_sizes, int n_in,
                              void* d_out, int out_size)
{
    const float* q  = (const float*)d_in[0];
    const float* k  = (const float*)d_in[1];
    const float* v  = (const float*)d_in[2];
    const float* Wq = (const float*)d_in[3];
    const float* bq = (const float*)d_in[4];
    const float* Wk = (const float*)d_in[5];
    const float* bk = (const float*)d_in[6];
    const float* Wv = (const float*)d_in[7];
    const float* bv = (const float*)d_in[8];
    const float* Wo = (const float*)d_in[9];
    const float* bo = (const float*)d_in[10];
    float* out = (float*)d_out;

    __half *qf, *kf, *vf, *yf;
    cudaGetSymbolAddress((void**)&qf, g_qf);
    cudaGetSymbolAddress((void**)&kf, g_kf);
    cudaGetSymbolAddress((void**)&vf, g_vf);
    cudaGetSymbolAddress((void**)&yf, g_yf);

    const size_t XN = (size_t)ROWS * DM;
    const size_t WN = (size_t)DM * DM;

    { const dim3 gi((unsigned)(XN/4/256), 1, 3);
      split_in<<<gi, 256>>>((const float4*)q, (const float4*)k, (const float4*)v); }
    { const dim3 gw((unsigned)(WN/4/256), 1, 4);
      split_w<<<gw, 256>>>((const float4*)Wq, (const float4*)Wk,
                           (const float4*)Wv, (const float4*)Wo); }

    cudaFuncSetAttribute((const void*)gemm_qkv16,
                         cudaFuncAttributeMaxDynamicSharedMemorySize, G16_SMEM);
    cudaFuncSetAttribute((const void*)gemm_out16,
                         cudaFuncAttributeMaxDynamicSharedMemorySize, G16_SMEM);
    const dim3 gq(DM/128, ROWS/128, 3);
    gemm_qkv16<<<gq, 256, G16_SMEM>>>(bq, bk, bv);

    const int asmem = QONE + 4 * ASTAGE;   // 92160
    cudaFuncSetAttribute((const void*)attn_mma,
                         cudaFuncAttributeMaxDynamicSharedMemorySize, asmem);
    const dim3 ga(SEQ/128, NH*NB);  // (16, 32)
    attn_mma<<<ga, 256, asmem>>>(qf, kf, vf, yf);

    const dim3 gg(DM/128, ROWS/128);
    gemm_out16<<<gg, 256, G16_SMEM>>>(bo, out);
}